// round 7
// baseline (speedup 1.0000x reference)
#include <cuda_runtime.h>
#include <stdint.h>

// Unpool (max_unpool_with_argmax) — inverse-scatter, one thread per input w-PAIR.
// val:  float32 [B=16, H=64, W=64, C=128]
// mask: int32   [B,H,W,C] — global flat index into output [B,128,128,128]
// out:  float32 [B,128,128,128]
//
// Thread handles input float4 groups (b,h,2wp,c4) and (b,h,2wp+1,c4):
//   4 front-batched streaming loads (MLP=4), then 8 independent coalesced
//   st.global.cg stores covering the 2x2 neighborhoods of both w positions.
// Warp = 32 consecutive c4: every load/store is a contiguous 512B segment;
// the 8 stores form two contiguous 2KB rows (dh=0 and dh=1).

__device__ __forceinline__ void stcg4(float* p, float4 v) {
    asm volatile("st.global.cg.v4.f32 [%0], {%1,%2,%3,%4};"
                 :: "l"(p), "f"(v.x), "f"(v.y), "f"(v.z), "f"(v.w) : "memory");
}
__device__ __forceinline__ float4 ldcs4f(const float* p) {
    float4 v;
    asm volatile("ld.global.cs.v4.f32 {%0,%1,%2,%3}, [%4];"
                 : "=f"(v.x), "=f"(v.y), "=f"(v.z), "=f"(v.w) : "l"(p));
    return v;
}
__device__ __forceinline__ int4 ldcs4i(const int* p) {
    int4 v;
    asm volatile("ld.global.cs.v4.s32 {%0,%1,%2,%3}, [%4];"
                 : "=r"(v.x), "=r"(v.y), "=r"(v.z), "=r"(v.w) : "l"(p));
    return v;
}

__device__ __forceinline__ float4 sel4(int4 m, float4 v, int f) {
    float4 r;
    r.x = (m.x == f    ) ? v.x : 0.0f;
    r.y = (m.y == f + 1) ? v.y : 0.0f;
    r.z = (m.z == f + 2) ? v.z : 0.0f;
    r.w = (m.w == f + 3) ? v.w : 0.0f;
    return r;
}

__global__ __launch_bounds__(256)
void unpool_scatter8_i32(const float* __restrict__ val,
                         const int*   __restrict__ mask,
                         float* __restrict__ out)
{
    unsigned int i = blockIdx.x * blockDim.x + threadIdx.x;  // w-pair id

    unsigned int c4 = i & 31u;          // channel group [0,32)
    unsigned int wp = (i >> 5) & 31u;   // w-pair       [0,32)  -> w = 2wp, 2wp+1
    unsigned int h  = (i >> 10) & 63u;
    unsigned int b  = i >> 16;

    // input float index of (b,h,2wp,c4*4); w stride = 128
    unsigned int in0 = b * 524288u + h * 8192u + wp * 256u + (c4 << 2);

    // 4 independent streaming loads, front-batched
    float4 v0 = ldcs4f(val  + in0);
    float4 v1 = ldcs4f(val  + in0 + 128u);
    int4   m0 = ldcs4i(mask + in0);
    int4   m1 = ldcs4i(mask + in0 + 128u);

    // output float index of (b, 2h, 4wp, c4*4)
    unsigned int base = b * 2097152u + h * 32768u + wp * 512u + (c4 << 2);

    // w0 = 2wp: offsets 0 /128 (dw) /16384 (dh) /16512
    // w1 = 2wp+1: +256 relative, same dw/dh offsets
    float4 r00 = sel4(m0, v0, (int)base);
    float4 r01 = sel4(m0, v0, (int)base + 128);
    float4 r10 = sel4(m0, v0, (int)base + 16384);
    float4 r11 = sel4(m0, v0, (int)base + 16512);
    float4 s00 = sel4(m1, v1, (int)base + 256);
    float4 s01 = sel4(m1, v1, (int)base + 384);
    float4 s10 = sel4(m1, v1, (int)base + 16640);
    float4 s11 = sel4(m1, v1, (int)base + 16768);

    float* o = out + base;
    stcg4(o,          r00);
    stcg4(o + 128u,   r01);
    stcg4(o + 256u,   s00);
    stcg4(o + 384u,   s01);
    stcg4(o + 16384u, r10);
    stcg4(o + 16512u, r11);
    stcg4(o + 16640u, s10);
    stcg4(o + 16768u, s11);
}

// int64-mask fallback (dtype robustness; single-group variant)
__global__ __launch_bounds__(256)
void unpool_scatter4_i64(const float* __restrict__ val,
                         const long long* __restrict__ mask,
                         float* __restrict__ out)
{
    unsigned int i = blockIdx.x * blockDim.x + threadIdx.x;

    unsigned int c4 = i & 31u;
    unsigned int w  = (i >> 5) & 63u;
    unsigned int h  = (i >> 11) & 63u;
    unsigned int b  = i >> 17;

    float4 v = *reinterpret_cast<const float4*>(val + ((size_t)i << 2));
    longlong2 m01 = *reinterpret_cast<const longlong2*>(mask + ((size_t)i << 2));
    longlong2 m23 = *reinterpret_cast<const longlong2*>(mask + ((size_t)i << 2) + 2);

    unsigned int base0 = b * 2097152u + h * 32768u + w * 256u + (c4 << 2);

    long long mm[4] = { m01.x, m01.y, m23.x, m23.y };
    float     vv[4] = { v.x, v.y, v.z, v.w };
    unsigned int off[4] = { 0u, 128u, 16384u, 16512u };

    #pragma unroll
    for (int p = 0; p < 4; p++) {
        long long f = (long long)(base0 + off[p]);
        float4 r;
        r.x = (mm[0] == f    ) ? vv[0] : 0.0f;
        r.y = (mm[1] == f + 1) ? vv[1] : 0.0f;
        r.z = (mm[2] == f + 2) ? vv[2] : 0.0f;
        r.w = (mm[3] == f + 3) ? vv[3] : 0.0f;
        stcg4(out + base0 + off[p], r);
    }
}

extern "C" void kernel_launch(void* const* d_in, const int* in_sizes, int n_in,
                              void* d_out, int out_size)
{
    const float* val = (const float*)d_in[0];
    float*       out = (float*)d_out;

    if (n_in >= 2 && in_sizes[1] == 2 * in_sizes[0]) {
        const unsigned int n4 = 2097152u;
        unpool_scatter4_i64<<<n4 / 256u, 256u>>>(val, (const long long*)d_in[1], out);
    } else {
        const unsigned int npairs = 1048576u;  // 16*64*32*32 w-pair threads
        unpool_scatter8_i32<<<npairs / 256u, 256u>>>(val, (const int*)d_in[1], out);
    }
}

// round 8
// speedup vs baseline: 1.0411x; 1.0411x over previous
#include <cuda_runtime.h>
#include <stdint.h>

// Unpool (max_unpool_with_argmax) — inverse-scatter, one thread per input w-PAIR.
// val:  float32 [B=16, H=64, W=64, C=128]
// mask: int32   [B,H,W,C] — global flat index into output [B,128,128,128]
// out:  float32 [B,128,128,128]
//
// Thread handles input float4 groups (b,h,2wp,c4) and (b,h,2wp+1,c4):
//   4 front-batched streaming loads (MLP=4), then 8 independent coalesced
//   st.global.cg stores covering the 2x2 neighborhoods of both w positions.
// Warp = 32 consecutive c4: every load/store is a contiguous 512B segment;
// the 8 stores form two contiguous 2KB rows (dh=0 and dh=1).

__device__ __forceinline__ void stcg4(float* p, float4 v) {
    asm volatile("st.global.cg.v4.f32 [%0], {%1,%2,%3,%4};"
                 :: "l"(p), "f"(v.x), "f"(v.y), "f"(v.z), "f"(v.w) : "memory");
}
__device__ __forceinline__ float4 ldcs4f(const float* p) {
    float4 v;
    asm volatile("ld.global.cs.v4.f32 {%0,%1,%2,%3}, [%4];"
                 : "=f"(v.x), "=f"(v.y), "=f"(v.z), "=f"(v.w) : "l"(p));
    return v;
}
__device__ __forceinline__ int4 ldcs4i(const int* p) {
    int4 v;
    asm volatile("ld.global.cs.v4.s32 {%0,%1,%2,%3}, [%4];"
                 : "=r"(v.x), "=r"(v.y), "=r"(v.z), "=r"(v.w) : "l"(p));
    return v;
}

__device__ __forceinline__ float4 sel4(int4 m, float4 v, int f) {
    float4 r;
    r.x = (m.x == f    ) ? v.x : 0.0f;
    r.y = (m.y == f + 1) ? v.y : 0.0f;
    r.z = (m.z == f + 2) ? v.z : 0.0f;
    r.w = (m.w == f + 3) ? v.w : 0.0f;
    return r;
}

__global__ __launch_bounds__(256)
void unpool_scatter8_i32(const float* __restrict__ val,
                         const int*   __restrict__ mask,
                         float* __restrict__ out)
{
    unsigned int i = blockIdx.x * blockDim.x + threadIdx.x;  // w-pair id

    unsigned int c4 = i & 31u;          // channel group [0,32)
    unsigned int wp = (i >> 5) & 31u;   // w-pair       [0,32)  -> w = 2wp, 2wp+1
    unsigned int h  = (i >> 10) & 63u;
    unsigned int b  = i >> 16;

    // input float index of (b,h,2wp,c4*4); w stride = 128
    unsigned int in0 = b * 524288u + h * 8192u + wp * 256u + (c4 << 2);

    // 4 independent streaming loads, front-batched
    float4 v0 = ldcs4f(val  + in0);
    float4 v1 = ldcs4f(val  + in0 + 128u);
    int4   m0 = ldcs4i(mask + in0);
    int4   m1 = ldcs4i(mask + in0 + 128u);

    // output float index of (b, 2h, 4wp, c4*4)
    unsigned int base = b * 2097152u + h * 32768u + wp * 512u + (c4 << 2);

    // w0 = 2wp: offsets 0 /128 (dw) /16384 (dh) /16512
    // w1 = 2wp+1: +256 relative, same dw/dh offsets
    float4 r00 = sel4(m0, v0, (int)base);
    float4 r01 = sel4(m0, v0, (int)base + 128);
    float4 r10 = sel4(m0, v0, (int)base + 16384);
    float4 r11 = sel4(m0, v0, (int)base + 16512);
    float4 s00 = sel4(m1, v1, (int)base + 256);
    float4 s01 = sel4(m1, v1, (int)base + 384);
    float4 s10 = sel4(m1, v1, (int)base + 16640);
    float4 s11 = sel4(m1, v1, (int)base + 16768);

    float* o = out + base;
    stcg4(o,          r00);
    stcg4(o + 128u,   r01);
    stcg4(o + 256u,   s00);
    stcg4(o + 384u,   s01);
    stcg4(o + 16384u, r10);
    stcg4(o + 16512u, r11);
    stcg4(o + 16640u, s10);
    stcg4(o + 16768u, s11);
}

// int64-mask fallback (dtype robustness; single-group variant)
__global__ __launch_bounds__(256)
void unpool_scatter4_i64(const float* __restrict__ val,
                         const long long* __restrict__ mask,
                         float* __restrict__ out)
{
    unsigned int i = blockIdx.x * blockDim.x + threadIdx.x;

    unsigned int c4 = i & 31u;
    unsigned int w  = (i >> 5) & 63u;
    unsigned int h  = (i >> 11) & 63u;
    unsigned int b  = i >> 17;

    float4 v = *reinterpret_cast<const float4*>(val + ((size_t)i << 2));
    longlong2 m01 = *reinterpret_cast<const longlong2*>(mask + ((size_t)i << 2));
    longlong2 m23 = *reinterpret_cast<const longlong2*>(mask + ((size_t)i << 2) + 2);

    unsigned int base0 = b * 2097152u + h * 32768u + w * 256u + (c4 << 2);

    long long mm[4] = { m01.x, m01.y, m23.x, m23.y };
    float     vv[4] = { v.x, v.y, v.z, v.w };
    unsigned int off[4] = { 0u, 128u, 16384u, 16512u };

    #pragma unroll
    for (int p = 0; p < 4; p++) {
        long long f = (long long)(base0 + off[p]);
        float4 r;
        r.x = (mm[0] == f    ) ? vv[0] : 0.0f;
        r.y = (mm[1] == f + 1) ? vv[1] : 0.0f;
        r.z = (mm[2] == f + 2) ? vv[2] : 0.0f;
        r.w = (mm[3] == f + 3) ? vv[3] : 0.0f;
        stcg4(out + base0 + off[p], r);
    }
}

extern "C" void kernel_launch(void* const* d_in, const int* in_sizes, int n_in,
                              void* d_out, int out_size)
{
    const float* val = (const float*)d_in[0];
    float*       out = (float*)d_out;

    if (n_in >= 2 && in_sizes[1] == 2 * in_sizes[0]) {
        const unsigned int n4 = 2097152u;
        unpool_scatter4_i64<<<n4 / 256u, 256u>>>(val, (const long long*)d_in[1], out);
    } else {
        const unsigned int npairs = 1048576u;  // 16*64*32*32 w-pair threads
        unpool_scatter8_i32<<<npairs / 256u, 256u>>>(val, (const int*)d_in[1], out);
    }
}